// round 11
// baseline (speedup 1.0000x reference)
#include <cuda_runtime.h>
#include <math.h>

#define KPTS 20
#define KP3  23
#define OUT_H 64
#define OUT_W 256
#define NPIX (OUT_H*OUT_W)   // 16384
#define BATCH 128
#define IN_H 128
#define IN_W 512
#define BG 2                 // batches per block in sampler

__device__ float g_glift[KP3*NPIX];   // transposed: [i][n]
__device__ float g_T[BATCH*KP3*2];    // [b][i][c]  (pre-scaled by W/H)

// ===================== compile-time INV_DELTA (constexpr f64) =====================
__host__ __device__ constexpr double cpt_x(int k) {
    int j = (k < KPTS/2) ? k : (k - KPTS/2);
    double step = (0.95 - 0.05) / 9.0;
    return (j == 9) ? 0.95 : 0.05 + (double)j * step;
}
__host__ __device__ constexpr double cpt_y(int k) { return (k < KPTS/2) ? 0.05 : 0.95; }

constexpr double csqrt(double x) {
    double y = (x > 1.0) ? x : 1.0;
    for (int i = 0; i < 40; ++i) y = 0.5 * (y + x / y);
    return y;
}
constexpr double clog(double x) {
    double r = csqrt(csqrt(x));
    double s = (r - 1.0) / (r + 1.0);
    double z = s * s;
    double sum = 0.0, term = s;
    for (int n = 0; n < 26; ++n) {
        sum += term / (double)(2*n + 1);
        term *= z;
    }
    return 8.0 * sum;
}

struct InvMat { float m[KP3*KP3]; };

constexpr InvMat make_inv() {
    double A[KP3][2*KP3] = {};
    for (int r = 0; r < KP3; ++r)
        for (int c = 0; c < KP3; ++c) {
            double v = 0.0;
            if (r < KPTS) {
                if (c == 0) v = 1.0;
                else if (c == 1) v = cpt_x(r);
                else if (c == 2) v = cpt_y(r);
                else {
                    int k2 = c - 3;
                    if (r == k2) v = 0.0;
                    else {
                        double dx = cpt_x(r) - cpt_x(k2);
                        double dy = cpt_y(r) - cpt_y(k2);
                        double d = csqrt(dx*dx + dy*dy);
                        v = d*d*clog(d);
                    }
                }
            } else if (r == 20) { v = (c >= 3) ? cpt_x(c-3) : 0.0; }
            else if (r == 21)   { v = (c >= 3) ? cpt_y(c-3) : 0.0; }
            else                { v = (c >= 3) ? 1.0 : 0.0; }
            A[r][c] = v;
            A[r][KP3 + c] = (r == c) ? 1.0 : 0.0;
        }
    for (int p = 0; p < KP3; ++p) {
        int best = p; double bv = A[p][p] < 0 ? -A[p][p] : A[p][p];
        for (int r = p+1; r < KP3; ++r) {
            double v = A[r][p] < 0 ? -A[r][p] : A[r][p];
            if (v > bv) { bv = v; best = r; }
        }
        if (best != p)
            for (int c = 0; c < 2*KP3; ++c) {
                double t = A[p][c]; A[p][c] = A[best][c]; A[best][c] = t;
            }
        double ip = 1.0 / A[p][p];
        for (int c = 0; c < 2*KP3; ++c) A[p][c] *= ip;
        for (int r = 0; r < KP3; ++r) {
            if (r == p) continue;
            double f = A[r][p];
            for (int c = 0; c < 2*KP3; ++c) A[r][c] -= f * A[p][c];
        }
    }
    InvMat out{};
    for (int r = 0; r < KP3; ++r)
        for (int c = 0; c < KP3; ++c)
            out.m[r*KP3+c] = (float)A[r][KP3+c];
    return out;
}

__device__ constexpr InvMat g_invmat = make_inv();

// ======================= double-single (float-float) helpers =======================
struct DS { float h, l; };

__device__ __forceinline__ DS ds_norm(float h, float l) {
    float s = h + l;
    float e = l - (s - h);
    return {s, e};
}
__device__ __forceinline__ DS ds_add(DS a, DS b) {
    float s = a.h + b.h;
    float v = s - a.h;
    float e = (a.h - (s - v)) + (b.h - v);
    e += a.l + b.l;
    return ds_norm(s, e);
}
__device__ __forceinline__ DS ds_mul(DS a, DS b) {
    float p = a.h * b.h;
    float e = fmaf(a.h, b.h, -p);
    e = fmaf(a.h, b.l, e);
    e = fmaf(a.l, b.h, e);
    return ds_norm(p, e);
}
__device__ __forceinline__ DS ds_div(DS a, DS b) {
    float q = a.h / b.h;
    float p = q * b.h;
    float pe = fmaf(q, b.h, -p);
    float s = a.h - p;
    float v = s - a.h;
    float e = (a.h - (s - v)) + ((-p) - v);
    e += a.l - pe - q * b.l;
    float ql = (s + e) / b.h;
    return ds_norm(q, ql);
}
__device__ __forceinline__ DS ds_sqrt(DS t) {
    float y = sqrtf(t.h);
    float p = y * y;
    float pe = fmaf(y, y, -p);
    float s = t.h - p;
    float v = s - t.h;
    float e = (t.h - (s - v)) + ((-p) - v);
    e += t.l - pe;
    float corr = (s + e) / (2.0f * y);
    return ds_norm(y, corr);
}
__device__ __forceinline__ DS ds_log(DS a) {
    int ix = __float_as_int(a.h);
    int e = ((ix >> 23) & 0xFF) - 127;
    float sc = __int_as_float((127 - e) << 23);
    float mh = a.h * sc;
    float ml = a.l * sc;
    if (mh > 1.41421356f) { mh *= 0.5f; ml *= 0.5f; e += 1; }
    DS r = ds_norm(mh - 1.0f, ml);
    DS den = ds_add({2.0f, 0.0f}, r);
    DS s = ds_div(r, den);
    float z = s.h * s.h;
    float c = fmaf(z, 0.15384615f, 0.18181818f);
    c = fmaf(z, c, 0.22222222f);
    c = fmaf(z, c, 0.28571429f);
    c = fmaf(z, c, 0.4f);
    c = fmaf(z, c, 0.66666667f);
    c *= z;
    DS logm = ds_add({2.0f * s.h, 2.0f * s.l}, {s.h * c, 0.0f});
    float fe = (float)e;
    DS elog2 = {fe * 0.693145751953125f, fe * 1.4286068203094172e-06f};
    return ds_add(elog2, logm);
}

// ---------- 1. fully parallel prep: one thread per (pixel, k) RBF ----------
#define PREP_RBF_BLOCKS  (NPIX*KPTS/256)           // 1280
#define PREP_AFF_BLOCKS  (NPIX*3/256)              // 192
#define PREP_T_BLOCKS    ((BATCH*KP3*2 + 255)/256) // 23
#define PREP_BLOCKS      (PREP_RBF_BLOCKS + PREP_AFF_BLOCKS + PREP_T_BLOCKS)

__global__ __launch_bounds__(256) void k_prep(const float* __restrict__ ctrl) {
    int blk = blockIdx.x;
    if (blk < PREP_RBF_BLOCKS) {
        int id = blk*256 + threadIdx.x;
        int n = id & (NPIX-1);
        int k = id >> 14;                       // NPIX = 2^14
        int x = n & (OUT_W-1), y = n >> 8;
        float gx = ((float)x + 0.5f) * (1.0f/256.0f);
        float gy = ((float)y + 0.5f) * (1.0f/64.0f);

        constexpr double step = (0.95 - 0.05) / 9.0;
        int j = (k < KPTS/2) ? k : (k - KPTS/2);
        double cxd = (j == 9) ? 0.95 : 0.05 + (double)j * step;
        double cyd = (k < KPTS/2) ? 0.05 : 0.95;
        float cxh = (float)cxd, cxl = (float)(cxd - (double)cxh);
        float cyh = (float)cyd, cyl = (float)(cyd - (double)cyh);

        const DS EPS = {1e-6f, -1.1686097e-14f};
        DS dx = ds_add({gx, 0.0f}, {-cxh, -cxl});
        DS dy = ds_add({gy, 0.0f}, {-cyh, -cyl});
        DS t  = ds_add(ds_mul(dx, dx), ds_mul(dy, dy));
        DS d  = ds_sqrt(t);
        DS lg = ds_log(ds_add(d, EPS));
        DS v  = ds_mul(ds_mul(d, d), lg);
        g_glift[(3+k)*NPIX + n] = v.h;
    } else if (blk < PREP_RBF_BLOCKS + PREP_AFF_BLOCKS) {
        int id = (blk - PREP_RBF_BLOCKS)*256 + threadIdx.x;
        int n = id & (NPIX-1);
        int row = id >> 14;
        int x = n & (OUT_W-1), y = n >> 8;
        float val = 1.0f;
        if (row == 1) val = ((float)x + 0.5f) * (1.0f/256.0f);
        if (row == 2) val = ((float)y + 0.5f) * (1.0f/64.0f);
        g_glift[row*NPIX + n] = val;
    } else {
        int idx = (blk - PREP_RBF_BLOCKS - PREP_AFF_BLOCKS)*256 + threadIdx.x;
        if (idx < BATCH*KP3*2) {
            int b = idx / (KP3*2);
            int t = idx - b*(KP3*2);
            int i = t >> 1, c = t & 1;
            float acc = 0.f;
            #pragma unroll
            for (int j2 = 0; j2 < KPTS; ++j2)
                acc = fmaf(g_invmat.m[i*KP3+j2], __ldg(&ctrl[b*KPTS*2 + j2*2 + c]), acc);
            // fold the grid scale (W for x, H for y) into T
            g_T[idx] = acc * (c == 0 ? (float)IN_W : (float)IN_H);
        }
    }
}

// ---------- 2. sampler: R7 structure, BG=2, 6 CTAs/SM ----------
__global__ __launch_bounds__(OUT_W, 6) void k_sample(const float* __restrict__ X,
                                                     float* __restrict__ out) {
    int y    = blockIdx.x;            // 0..63
    int b0   = blockIdx.y * BG;       // batch group
    int tid  = threadIdx.x;           // 0..255 (output x, = pixel owner)
    int warp = tid >> 5, lane = tid & 31;
    int n    = y*OUT_W + tid;

    __shared__ float2 Ts[BG*KP3];
    {
        const float2* gT2 = (const float2*)(g_T + b0*KP3*2);
        for (int t = tid; t < BG*KP3; t += blockDim.x)
            Ts[t] = gT2[t];
    }

    float gl[KP3];
    #pragma unroll
    for (int i = 0; i < KP3; ++i) gl[i] = g_glift[i*NPIX + n];
    __syncthreads();

    // phase 1: clamped coords for both batches (T pre-scaled by W/H)
    float cgx[BG], cgy[BG];
    #pragma unroll
    for (int bb = 0; bb < BG; ++bb) {
        const float2* tb = &Ts[bb*KP3];
        float gpx = 0.f, gpy = 0.f;
        #pragma unroll
        for (int i = 0; i < KP3; ++i) {
            float2 t2 = tb[i];
            gpx = fmaf(gl[i], t2.x, gpx);
            gpy = fmaf(gl[i], t2.y, gpy);
        }
        cgx[bb] = fminf(fmaxf(gpx, 0.f), (float)(IN_W-2));
        cgy[bb] = fminf(fmaxf(gpy, 0.f), (float)(IN_H-2));
    }

    // phase 2: gather, (pixel,channel) work items fed by shuffles
    #pragma unroll
    for (int bb = 0; bb < BG; ++bb) {
        int b = b0 + bb;
        float myGx = cgx[bb], myGy = cgy[bb];
        size_t obase = ((size_t)(b*OUT_H + y)*OUT_W + warp*32)*3;
        #pragma unroll
        for (int pass = 0; pass < 3; ++pass) {
            int i = pass*32 + lane;           // 0..95
            int p = i / 3;                     // source pixel (lane) in this warp
            int c = i - p*3;                   // channel
            float Gx = __shfl_sync(0xFFFFFFFFu, myGx, p);
            float Gy = __shfl_sync(0xFFFFFFFFu, myGy, p);
            float fx0 = floorf(Gx), fy0 = floorf(Gy);
            int x0 = (int)fx0, y0 = (int)fy0;
            float ax = Gx - fx0, bx = fx0 + 1.f - Gx;
            float ay = Gy - fy0, by = fy0 + 1.f - Gy;
            int ba = ((b*IN_H + y0)*IN_W + x0)*3 + c;
            float v00 = __ldg(X + ba);
            float v10 = __ldg(X + ba + 3);
            float v01 = __ldg(X + ba + IN_W*3);
            float v11 = __ldg(X + ba + IN_W*3 + 3);
            out[obase + i] = (bx*by)*v00 + (bx*ay)*v01 + (ax*by)*v10 + (ax*ay)*v11;
        }
    }
}

extern "C" void kernel_launch(void* const* d_in, const int* in_sizes, int n_in,
                              void* d_out, int out_size) {
    const float* X    = (const float*)d_in[0];
    const float* ctrl = (const float*)d_in[1];
    if (n_in >= 2 && in_sizes[0] == BATCH*KPTS*2) {   // defensive order swap
        X    = (const float*)d_in[1];
        ctrl = (const float*)d_in[0];
    }
    float* out = (float*)d_out;

    k_prep<<<PREP_BLOCKS, 256>>>(ctrl);
    dim3 grid(OUT_H, BATCH/BG);
    k_sample<<<grid, OUT_W>>>(X, out);
}

// round 12
// speedup vs baseline: 1.0192x; 1.0192x over previous
#include <cuda_runtime.h>
#include <math.h>

#define KPTS 20
#define KP3  23
#define OUT_H 64
#define OUT_W 256
#define NPIX (OUT_H*OUT_W)   // 16384
#define BATCH 128
#define IN_H 128
#define IN_W 512
#define BG 4                 // batches per block in sampler

__device__ float g_glift[KP3*NPIX];   // transposed: [i][n]
__device__ float g_T[BATCH*KP3*2];    // [b][i][c]  (pre-scaled by W/H)

// ===================== compile-time INV_DELTA (constexpr f64) =====================
__host__ __device__ constexpr double cpt_x(int k) {
    int j = (k < KPTS/2) ? k : (k - KPTS/2);
    double step = (0.95 - 0.05) / 9.0;
    return (j == 9) ? 0.95 : 0.05 + (double)j * step;
}
__host__ __device__ constexpr double cpt_y(int k) { return (k < KPTS/2) ? 0.05 : 0.95; }

constexpr double csqrt(double x) {
    double y = (x > 1.0) ? x : 1.0;
    for (int i = 0; i < 40; ++i) y = 0.5 * (y + x / y);
    return y;
}
constexpr double clog(double x) {
    double r = csqrt(csqrt(x));
    double s = (r - 1.0) / (r + 1.0);
    double z = s * s;
    double sum = 0.0, term = s;
    for (int n = 0; n < 26; ++n) {
        sum += term / (double)(2*n + 1);
        term *= z;
    }
    return 8.0 * sum;
}

struct InvMat { float m[KP3*KP3]; };

constexpr InvMat make_inv() {
    double A[KP3][2*KP3] = {};
    for (int r = 0; r < KP3; ++r)
        for (int c = 0; c < KP3; ++c) {
            double v = 0.0;
            if (r < KPTS) {
                if (c == 0) v = 1.0;
                else if (c == 1) v = cpt_x(r);
                else if (c == 2) v = cpt_y(r);
                else {
                    int k2 = c - 3;
                    if (r == k2) v = 0.0;
                    else {
                        double dx = cpt_x(r) - cpt_x(k2);
                        double dy = cpt_y(r) - cpt_y(k2);
                        double d = csqrt(dx*dx + dy*dy);
                        v = d*d*clog(d);
                    }
                }
            } else if (r == 20) { v = (c >= 3) ? cpt_x(c-3) : 0.0; }
            else if (r == 21)   { v = (c >= 3) ? cpt_y(c-3) : 0.0; }
            else                { v = (c >= 3) ? 1.0 : 0.0; }
            A[r][c] = v;
            A[r][KP3 + c] = (r == c) ? 1.0 : 0.0;
        }
    for (int p = 0; p < KP3; ++p) {
        int best = p; double bv = A[p][p] < 0 ? -A[p][p] : A[p][p];
        for (int r = p+1; r < KP3; ++r) {
            double v = A[r][p] < 0 ? -A[r][p] : A[r][p];
            if (v > bv) { bv = v; best = r; }
        }
        if (best != p)
            for (int c = 0; c < 2*KP3; ++c) {
                double t = A[p][c]; A[p][c] = A[best][c]; A[best][c] = t;
            }
        double ip = 1.0 / A[p][p];
        for (int c = 0; c < 2*KP3; ++c) A[p][c] *= ip;
        for (int r = 0; r < KP3; ++r) {
            if (r == p) continue;
            double f = A[r][p];
            for (int c = 0; c < 2*KP3; ++c) A[r][c] -= f * A[p][c];
        }
    }
    InvMat out{};
    for (int r = 0; r < KP3; ++r)
        for (int c = 0; c < KP3; ++c)
            out.m[r*KP3+c] = (float)A[r][KP3+c];
    return out;
}

__device__ constexpr InvMat g_invmat = make_inv();

// ======================= double-single (float-float) helpers =======================
struct DS { float h, l; };

__device__ __forceinline__ DS ds_norm(float h, float l) {
    float s = h + l;
    float e = l - (s - h);
    return {s, e};
}
__device__ __forceinline__ DS ds_add(DS a, DS b) {
    float s = a.h + b.h;
    float v = s - a.h;
    float e = (a.h - (s - v)) + (b.h - v);
    e += a.l + b.l;
    return ds_norm(s, e);
}
__device__ __forceinline__ DS ds_mul(DS a, DS b) {
    float p = a.h * b.h;
    float e = fmaf(a.h, b.h, -p);
    e = fmaf(a.h, b.l, e);
    e = fmaf(a.l, b.h, e);
    return ds_norm(p, e);
}
__device__ __forceinline__ DS ds_div(DS a, DS b) {
    float q = a.h / b.h;
    float p = q * b.h;
    float pe = fmaf(q, b.h, -p);
    float s = a.h - p;
    float v = s - a.h;
    float e = (a.h - (s - v)) + ((-p) - v);
    e += a.l - pe - q * b.l;
    float ql = (s + e) / b.h;
    return ds_norm(q, ql);
}
__device__ __forceinline__ DS ds_sqrt(DS t) {
    float y = sqrtf(t.h);
    float p = y * y;
    float pe = fmaf(y, y, -p);
    float s = t.h - p;
    float v = s - t.h;
    float e = (t.h - (s - v)) + ((-p) - v);
    e += t.l - pe;
    float corr = (s + e) / (2.0f * y);
    return ds_norm(y, corr);
}
__device__ __forceinline__ DS ds_log(DS a) {
    int ix = __float_as_int(a.h);
    int e = ((ix >> 23) & 0xFF) - 127;
    float sc = __int_as_float((127 - e) << 23);
    float mh = a.h * sc;
    float ml = a.l * sc;
    if (mh > 1.41421356f) { mh *= 0.5f; ml *= 0.5f; e += 1; }
    DS r = ds_norm(mh - 1.0f, ml);
    DS den = ds_add({2.0f, 0.0f}, r);
    DS s = ds_div(r, den);
    float z = s.h * s.h;
    float c = fmaf(z, 0.15384615f, 0.18181818f);
    c = fmaf(z, c, 0.22222222f);
    c = fmaf(z, c, 0.28571429f);
    c = fmaf(z, c, 0.4f);
    c = fmaf(z, c, 0.66666667f);
    c *= z;
    DS logm = ds_add({2.0f * s.h, 2.0f * s.l}, {s.h * c, 0.0f});
    float fe = (float)e;
    DS elog2 = {fe * 0.693145751953125f, fe * 1.4286068203094172e-06f};
    return ds_add(elog2, logm);
}

// ---------- 1. fully parallel prep: one thread per (pixel, k) RBF ----------
#define PREP_RBF_BLOCKS  (NPIX*KPTS/256)           // 1280
#define PREP_AFF_BLOCKS  (NPIX*3/256)              // 192
#define PREP_T_BLOCKS    ((BATCH*KP3*2 + 255)/256) // 23
#define PREP_BLOCKS      (PREP_RBF_BLOCKS + PREP_AFF_BLOCKS + PREP_T_BLOCKS)

__global__ __launch_bounds__(256) void k_prep(const float* __restrict__ ctrl) {
    int blk = blockIdx.x;
    if (blk < PREP_RBF_BLOCKS) {
        int id = blk*256 + threadIdx.x;
        int n = id & (NPIX-1);
        int k = id >> 14;                       // NPIX = 2^14
        int x = n & (OUT_W-1), y = n >> 8;
        float gx = ((float)x + 0.5f) * (1.0f/256.0f);
        float gy = ((float)y + 0.5f) * (1.0f/64.0f);

        constexpr double step = (0.95 - 0.05) / 9.0;
        int j = (k < KPTS/2) ? k : (k - KPTS/2);
        double cxd = (j == 9) ? 0.95 : 0.05 + (double)j * step;
        double cyd = (k < KPTS/2) ? 0.05 : 0.95;
        float cxh = (float)cxd, cxl = (float)(cxd - (double)cxh);
        float cyh = (float)cyd, cyl = (float)(cyd - (double)cyh);

        const DS EPS = {1e-6f, -1.1686097e-14f};
        DS dx = ds_add({gx, 0.0f}, {-cxh, -cxl});
        DS dy = ds_add({gy, 0.0f}, {-cyh, -cyl});
        DS t  = ds_add(ds_mul(dx, dx), ds_mul(dy, dy));
        DS d  = ds_sqrt(t);
        DS lg = ds_log(ds_add(d, EPS));
        DS v  = ds_mul(ds_mul(d, d), lg);
        g_glift[(3+k)*NPIX + n] = v.h;
    } else if (blk < PREP_RBF_BLOCKS + PREP_AFF_BLOCKS) {
        int id = (blk - PREP_RBF_BLOCKS)*256 + threadIdx.x;
        int n = id & (NPIX-1);
        int row = id >> 14;
        int x = n & (OUT_W-1), y = n >> 8;
        float val = 1.0f;
        if (row == 1) val = ((float)x + 0.5f) * (1.0f/256.0f);
        if (row == 2) val = ((float)y + 0.5f) * (1.0f/64.0f);
        g_glift[row*NPIX + n] = val;
    } else {
        int idx = (blk - PREP_RBF_BLOCKS - PREP_AFF_BLOCKS)*256 + threadIdx.x;
        if (idx < BATCH*KP3*2) {
            int b = idx / (KP3*2);
            int t = idx - b*(KP3*2);
            int i = t >> 1, c = t & 1;
            float acc = 0.f;
            #pragma unroll
            for (int j2 = 0; j2 < KPTS; ++j2)
                acc = fmaf(g_invmat.m[i*KP3+j2], __ldg(&ctrl[b*KPTS*2 + j2*2 + c]), acc);
            // fold the grid scale (W for x, H for y) into T
            g_T[idx] = acc * (c == 0 ? (float)IN_W : (float)IN_H);
        }
    }
}

// ---------- 2. sampler: R7 structure, BG=4, 5 CTAs/SM ----------
__global__ __launch_bounds__(OUT_W, 5) void k_sample(const float* __restrict__ X,
                                                     float* __restrict__ out) {
    int y    = blockIdx.x;            // 0..63
    int b0   = blockIdx.y * BG;       // batch group
    int tid  = threadIdx.x;           // 0..255 (output x, = pixel owner)
    int warp = tid >> 5, lane = tid & 31;
    int n    = y*OUT_W + tid;

    __shared__ float2 Ts[BG*KP3];
    {
        const float2* gT2 = (const float2*)(g_T + b0*KP3*2);
        for (int t = tid; t < BG*KP3; t += blockDim.x)
            Ts[t] = gT2[t];
    }

    float gl[KP3];
    #pragma unroll
    for (int i = 0; i < KP3; ++i) gl[i] = g_glift[i*NPIX + n];
    __syncthreads();

    // phase 1: clamped coords for all BG batches (T pre-scaled by W/H)
    float cgx[BG], cgy[BG];
    #pragma unroll
    for (int bb = 0; bb < BG; ++bb) {
        const float2* tb = &Ts[bb*KP3];
        float gpx = 0.f, gpy = 0.f;
        #pragma unroll
        for (int i = 0; i < KP3; ++i) {
            float2 t2 = tb[i];
            gpx = fmaf(gl[i], t2.x, gpx);
            gpy = fmaf(gl[i], t2.y, gpy);
        }
        cgx[bb] = fminf(fmaxf(gpx, 0.f), (float)(IN_W-2));
        cgy[bb] = fminf(fmaxf(gpy, 0.f), (float)(IN_H-2));
    }

    // phase 2: gather, (pixel,channel) work items fed by shuffles
    #pragma unroll
    for (int bb = 0; bb < BG; ++bb) {
        int b = b0 + bb;
        float myGx = cgx[bb], myGy = cgy[bb];
        size_t obase = ((size_t)(b*OUT_H + y)*OUT_W + warp*32)*3;
        #pragma unroll
        for (int pass = 0; pass < 3; ++pass) {
            int i = pass*32 + lane;           // 0..95
            int p = i / 3;                     // source pixel (lane) in this warp
            int c = i - p*3;                   // channel
            float Gx = __shfl_sync(0xFFFFFFFFu, myGx, p);
            float Gy = __shfl_sync(0xFFFFFFFFu, myGy, p);
            float fx0 = floorf(Gx), fy0 = floorf(Gy);
            int x0 = (int)fx0, y0 = (int)fy0;
            float ax = Gx - fx0, bx = fx0 + 1.f - Gx;
            float ay = Gy - fy0, by = fy0 + 1.f - Gy;
            int ba = ((b*IN_H + y0)*IN_W + x0)*3 + c;
            float v00 = __ldg(X + ba);
            float v10 = __ldg(X + ba + 3);
            float v01 = __ldg(X + ba + IN_W*3);
            float v11 = __ldg(X + ba + IN_W*3 + 3);
            out[obase + i] = (bx*by)*v00 + (bx*ay)*v01 + (ax*by)*v10 + (ax*ay)*v11;
        }
    }
}

extern "C" void kernel_launch(void* const* d_in, const int* in_sizes, int n_in,
                              void* d_out, int out_size) {
    const float* X    = (const float*)d_in[0];
    const float* ctrl = (const float*)d_in[1];
    if (n_in >= 2 && in_sizes[0] == BATCH*KPTS*2) {   // defensive order swap
        X    = (const float*)d_in[1];
        ctrl = (const float*)d_in[0];
    }
    float* out = (float*)d_out;

    k_prep<<<PREP_BLOCKS, 256>>>(ctrl);
    dim3 grid(OUT_H, BATCH/BG);
    k_sample<<<grid, OUT_W>>>(X, out);
}

// round 14
// speedup vs baseline: 1.0580x; 1.0381x over previous
#include <cuda_runtime.h>
#include <math.h>

#define KPTS 20
#define KP3  23
#define OUT_H 64
#define OUT_W 256
#define NPIX (OUT_H*OUT_W)   // 16384
#define BATCH 128
#define IN_H 128
#define IN_W 512
#define BG 4                 // batches per block in sampler

__device__ float g_glift[KP3*NPIX];   // transposed: [i][n]
__device__ float g_T[BATCH*KP3*2];    // [b][i][c]

// ===================== compile-time INV_DELTA (constexpr f64) =====================
__host__ __device__ constexpr double cpt_x(int k) {
    int j = (k < KPTS/2) ? k : (k - KPTS/2);
    double step = (0.95 - 0.05) / 9.0;
    return (j == 9) ? 0.95 : 0.05 + (double)j * step;
}
__host__ __device__ constexpr double cpt_y(int k) { return (k < KPTS/2) ? 0.05 : 0.95; }

constexpr double csqrt(double x) {
    double y = (x > 1.0) ? x : 1.0;
    for (int i = 0; i < 40; ++i) y = 0.5 * (y + x / y);
    return y;
}
constexpr double clog(double x) {
    double r = csqrt(csqrt(x));
    double s = (r - 1.0) / (r + 1.0);
    double z = s * s;
    double sum = 0.0, term = s;
    for (int n = 0; n < 26; ++n) {
        sum += term / (double)(2*n + 1);
        term *= z;
    }
    return 8.0 * sum;
}

struct InvMat { float m[KP3*KP3]; };

constexpr InvMat make_inv() {
    double A[KP3][2*KP3] = {};
    for (int r = 0; r < KP3; ++r)
        for (int c = 0; c < KP3; ++c) {
            double v = 0.0;
            if (r < KPTS) {
                if (c == 0) v = 1.0;
                else if (c == 1) v = cpt_x(r);
                else if (c == 2) v = cpt_y(r);
                else {
                    int k2 = c - 3;
                    if (r == k2) v = 0.0;
                    else {
                        double dx = cpt_x(r) - cpt_x(k2);
                        double dy = cpt_y(r) - cpt_y(k2);
                        double d = csqrt(dx*dx + dy*dy);
                        v = d*d*clog(d);
                    }
                }
            } else if (r == 20) { v = (c >= 3) ? cpt_x(c-3) : 0.0; }
            else if (r == 21)   { v = (c >= 3) ? cpt_y(c-3) : 0.0; }
            else                { v = (c >= 3) ? 1.0 : 0.0; }
            A[r][c] = v;
            A[r][KP3 + c] = (r == c) ? 1.0 : 0.0;
        }
    for (int p = 0; p < KP3; ++p) {
        int best = p; double bv = A[p][p] < 0 ? -A[p][p] : A[p][p];
        for (int r = p+1; r < KP3; ++r) {
            double v = A[r][p] < 0 ? -A[r][p] : A[r][p];
            if (v > bv) { bv = v; best = r; }
        }
        if (best != p)
            for (int c = 0; c < 2*KP3; ++c) {
                double t = A[p][c]; A[p][c] = A[best][c]; A[best][c] = t;
            }
        double ip = 1.0 / A[p][p];
        for (int c = 0; c < 2*KP3; ++c) A[p][c] *= ip;
        for (int r = 0; r < KP3; ++r) {
            if (r == p) continue;
            double f = A[r][p];
            for (int c = 0; c < 2*KP3; ++c) A[r][c] -= f * A[p][c];
        }
    }
    InvMat out{};
    for (int r = 0; r < KP3; ++r)
        for (int c = 0; c < KP3; ++c)
            out.m[r*KP3+c] = (float)A[r][KP3+c];
    return out;
}

__device__ constexpr InvMat g_invmat = make_inv();

// ======================= double-single (float-float) helpers =======================
// Correction-term divides use __fdividef (2^-21): residuals are re-corrected, so
// end-to-end accuracy stays ~2^-42 — far beyond the ~2^-30 the TPS system needs.
struct DS { float h, l; };

__device__ __forceinline__ DS ds_norm(float h, float l) {
    float s = h + l;
    float e = l - (s - h);
    return {s, e};
}
__device__ __forceinline__ DS ds_add(DS a, DS b) {
    float s = a.h + b.h;
    float v = s - a.h;
    float e = (a.h - (s - v)) + (b.h - v);
    e += a.l + b.l;
    return ds_norm(s, e);
}
__device__ __forceinline__ DS ds_mul(DS a, DS b) {
    float p = a.h * b.h;
    float e = fmaf(a.h, b.h, -p);
    e = fmaf(a.h, b.l, e);
    e = fmaf(a.l, b.h, e);
    return ds_norm(p, e);
}
__device__ __forceinline__ DS ds_div(DS a, DS b) {
    float q = __fdividef(a.h, b.h);
    float p = q * b.h;
    float pe = fmaf(q, b.h, -p);
    float s = a.h - p;
    float v = s - a.h;
    float e = (a.h - (s - v)) + ((-p) - v);
    e += a.l - pe - q * b.l;
    float ql = __fdividef(s + e, b.h);
    return ds_norm(q, ql);
}
__device__ __forceinline__ DS ds_sqrt(DS t) {
    float y = sqrtf(t.h);
    float p = y * y;
    float pe = fmaf(y, y, -p);
    float s = t.h - p;
    float v = s - t.h;
    float e = (t.h - (s - v)) + ((-p) - v);
    e += t.l - pe;
    float corr = __fdividef(s + e, 2.0f * y);
    return ds_norm(y, corr);
}
__device__ __forceinline__ DS ds_log(DS a) {
    int ix = __float_as_int(a.h);
    int e = ((ix >> 23) & 0xFF) - 127;
    float sc = __int_as_float((127 - e) << 23);
    float mh = a.h * sc;
    float ml = a.l * sc;
    if (mh > 1.41421356f) { mh *= 0.5f; ml *= 0.5f; e += 1; }
    DS r = ds_norm(mh - 1.0f, ml);
    DS den = ds_add({2.0f, 0.0f}, r);
    DS s = ds_div(r, den);
    float z = s.h * s.h;
    float c = fmaf(z, 0.15384615f, 0.18181818f);
    c = fmaf(z, c, 0.22222222f);
    c = fmaf(z, c, 0.28571429f);
    c = fmaf(z, c, 0.4f);
    c = fmaf(z, c, 0.66666667f);
    c *= z;
    DS logm = ds_add({2.0f * s.h, 2.0f * s.l}, {s.h * c, 0.0f});
    float fe = (float)e;
    DS elog2 = {fe * 0.693145751953125f, fe * 1.4286068203094172e-06f};
    return ds_add(elog2, logm);
}

// ---------- 1. fully parallel prep: one thread per (pixel, k) RBF ----------
#define PREP_RBF_BLOCKS  (NPIX*KPTS/256)           // 1280
#define PREP_AFF_BLOCKS  (NPIX*3/256)              // 192
#define PREP_T_BLOCKS    ((BATCH*KP3*2 + 255)/256) // 23
#define PREP_BLOCKS      (PREP_RBF_BLOCKS + PREP_AFF_BLOCKS + PREP_T_BLOCKS)

__global__ __launch_bounds__(256) void k_prep(const float* __restrict__ ctrl) {
    int blk = blockIdx.x;
    if (blk < PREP_RBF_BLOCKS) {
        int id = blk*256 + threadIdx.x;
        int n = id & (NPIX-1);
        int k = id >> 14;                       // NPIX = 2^14
        int x = n & (OUT_W-1), y = n >> 8;
        float gx = ((float)x + 0.5f) * (1.0f/256.0f);
        float gy = ((float)y + 0.5f) * (1.0f/64.0f);

        constexpr double step = (0.95 - 0.05) / 9.0;
        int j = (k < KPTS/2) ? k : (k - KPTS/2);
        double cxd = (j == 9) ? 0.95 : 0.05 + (double)j * step;
        double cyd = (k < KPTS/2) ? 0.05 : 0.95;
        float cxh = (float)cxd, cxl = (float)(cxd - (double)cxh);
        float cyh = (float)cyd, cyl = (float)(cyd - (double)cyh);

        const DS EPS = {1e-6f, -1.1686097e-14f};
        DS dx = ds_add({gx, 0.0f}, {-cxh, -cxl});
        DS dy = ds_add({gy, 0.0f}, {-cyh, -cyl});
        DS t  = ds_add(ds_mul(dx, dx), ds_mul(dy, dy));
        DS d  = ds_sqrt(t);
        DS lg = ds_log(ds_add(d, EPS));
        DS v  = ds_mul(ds_mul(d, d), lg);
        g_glift[(3+k)*NPIX + n] = v.h;
    } else if (blk < PREP_RBF_BLOCKS + PREP_AFF_BLOCKS) {
        int id = (blk - PREP_RBF_BLOCKS)*256 + threadIdx.x;
        int n = id & (NPIX-1);
        int row = id >> 14;
        int x = n & (OUT_W-1), y = n >> 8;
        float val = 1.0f;
        if (row == 1) val = ((float)x + 0.5f) * (1.0f/256.0f);
        if (row == 2) val = ((float)y + 0.5f) * (1.0f/64.0f);
        g_glift[row*NPIX + n] = val;
    } else {
        int idx = (blk - PREP_RBF_BLOCKS - PREP_AFF_BLOCKS)*256 + threadIdx.x;
        if (idx < BATCH*KP3*2) {
            int b = idx / (KP3*2);
            int t = idx - b*(KP3*2);
            int i = t >> 1, c = t & 1;
            float acc = 0.f;
            #pragma unroll
            for (int j2 = 0; j2 < KPTS; ++j2)
                acc = fmaf(g_invmat.m[i*KP3+j2], __ldg(&ctrl[b*KPTS*2 + j2*2 + c]), acc);
            g_T[idx] = acc;
        }
    }
}

// ---------- 2. sampler: exact R7 configuration ----------
__global__ __launch_bounds__(OUT_W, 4) void k_sample(const float* __restrict__ X,
                                                     float* __restrict__ out) {
    int y    = blockIdx.x;            // 0..63
    int b0   = blockIdx.y * BG;       // batch group
    int tid  = threadIdx.x;           // 0..255 (output x, = pixel owner)
    int warp = tid >> 5, lane = tid & 31;
    int n    = y*OUT_W + tid;

    __shared__ float2 Ts[BG*KP3];
    {
        const float2* gT2 = (const float2*)(g_T + b0*KP3*2);
        for (int t = tid; t < BG*KP3; t += blockDim.x)
            Ts[t] = gT2[t];
    }

    float gl[KP3];
    #pragma unroll
    for (int i = 0; i < KP3; ++i) gl[i] = g_glift[i*NPIX + n];
    __syncthreads();

    // phase 1: clamped sampling coords for all BG batches
    float cgx[BG], cgy[BG];
    #pragma unroll
    for (int bb = 0; bb < BG; ++bb) {
        const float2* tb = &Ts[bb*KP3];
        float gpx = 0.f, gpy = 0.f;
        #pragma unroll
        for (int i = 0; i < KP3; ++i) {
            float2 t2 = tb[i];
            gpx = fmaf(gl[i], t2.x, gpx);
            gpy = fmaf(gl[i], t2.y, gpy);
        }
        cgx[bb] = fminf(fmaxf((float)IN_W * gpx, 0.f), (float)(IN_W-2));
        cgy[bb] = fminf(fmaxf((float)IN_H * gpy, 0.f), (float)(IN_H-2));
    }

    // phase 2: gather, (pixel,channel) work items fed by shuffles
    #pragma unroll
    for (int bb = 0; bb < BG; ++bb) {
        int b = b0 + bb;
        float myGx = cgx[bb], myGy = cgy[bb];
        size_t obase = ((size_t)(b*OUT_H + y)*OUT_W + warp*32)*3;
        #pragma unroll
        for (int pass = 0; pass < 3; ++pass) {
            int i = pass*32 + lane;           // 0..95
            int p = i / 3;                     // source pixel (lane) in this warp
            int c = i - p*3;                   // channel
            float Gx = __shfl_sync(0xFFFFFFFFu, myGx, p);
            float Gy = __shfl_sync(0xFFFFFFFFu, myGy, p);
            float fx0 = floorf(Gx), fy0 = floorf(Gy);
            int x0 = (int)fx0, y0 = (int)fy0;
            float ax = Gx - fx0, bx = fx0 + 1.f - Gx;
            float ay = Gy - fy0, by = fy0 + 1.f - Gy;
            int ba = ((b*IN_H + y0)*IN_W + x0)*3 + c;
            float v00 = __ldg(X + ba);
            float v10 = __ldg(X + ba + 3);
            float v01 = __ldg(X + ba + IN_W*3);
            float v11 = __ldg(X + ba + IN_W*3 + 3);
            out[obase + i] = (bx*by)*v00 + (bx*ay)*v01 + (ax*by)*v10 + (ax*ay)*v11;
        }
    }
}

extern "C" void kernel_launch(void* const* d_in, const int* in_sizes, int n_in,
                              void* d_out, int out_size) {
    const float* X    = (const float*)d_in[0];
    const float* ctrl = (const float*)d_in[1];
    if (n_in >= 2 && in_sizes[0] == BATCH*KPTS*2) {   // defensive order swap
        X    = (const float*)d_in[1];
        ctrl = (const float*)d_in[0];
    }
    float* out = (float*)d_out;

    k_prep<<<PREP_BLOCKS, 256>>>(ctrl);
    dim3 grid(OUT_H, BATCH/BG);
    k_sample<<<grid, OUT_W>>>(X, out);
}